// round 12
// baseline (speedup 1.0000x reference)
#include <cuda_runtime.h>
#include <cuda_bf16.h>
#include <math.h>

#define B 16
#define NTOT 17064
#define NQ   (NTOT/4)        /* 4266 threads per batch, 4 anchors each */
#define KSEL 1000
#define MAXOUT 100
#define SCORE_THR 0.05f
#define IOU_THR 0.6f
#define CANDCAP 2048
#define FASTN 128

typedef unsigned long long u64;

// ---------------- scratch (static device globals; no allocations) ----------------
__device__ u64      g_key[B * NTOT];
__device__ float4   g_box[B * NTOT];   // written sparsely (candidates only)
__device__ int      g_cls[B * NTOT];   // written sparsely (candidates only)
__device__ unsigned g_hist[B * 1024];  // zero-init at load; re-zeroed by select
__device__ int      g_cnt[B];          // zero-init at load; re-zeroed by select
__device__ u64      g_cand[B * CANDCAP];

__device__ __forceinline__ void level_of(int a, int& p, int& hw, int& w, int& stride, int& lvl)
{
    if (a < 12800)      { p = a;         hw = 12800; w = 128; stride = 8;   lvl = 0; }
    else if (a < 16000) { p = a - 12800; hw = 3200;  w = 64;  stride = 16;  lvl = 1; }
    else if (a < 16800) { p = a - 16000; hw = 800;   w = 32;  stride = 32;  lvl = 2; }
    else if (a < 17008) { p = a - 16800; hw = 208;   w = 16;  stride = 64;  lvl = 3; }
    else                { p = a - 17008; hw = 56;    w = 8;   stride = 128; lvl = 4; }
}

// ---------------- kernel 1: decode = pure max-score stream (4 anchors/thread) ----------------
__global__ __launch_bounds__(256) void decode_kernel(
    const float* __restrict__ c0, const float* __restrict__ c1,
    const float* __restrict__ c2, const float* __restrict__ c3,
    const float* __restrict__ c4)
{
    int q = blockIdx.x * blockDim.x + threadIdx.x;
    if (q >= B * NQ) return;
    int b  = q / NQ;
    int a4 = (q - b * NQ) * 4;          // 4 consecutive anchors, same level/row

    int p, hw, w, stride, lvl;
    level_of(a4, p, hw, w, stride, lvl);
    const float* cp = (lvl == 0) ? c0 : (lvl == 1) ? c1 : (lvl == 2) ? c2 : (lvl == 3) ? c3 : c4;

    const int h4 = hw >> 2;
    const float4* cb4 = (const float4*)(cp + (size_t)b * 80 * hw + p);

    // index-free max chains (1 FMNMX per class per anchor)
    float m0 = -INFINITY, m1 = -INFINITY, m2 = -INFINITY, m3 = -INFINITY;
    #pragma unroll 8
    for (int c = 0; c < 80; c++) {
        float4 v = __ldg(cb4 + (size_t)c * h4);
        m0 = fmaxf(m0, v.x); m1 = fmaxf(m1, v.y);
        m2 = fmaxf(m2, v.z); m3 = fmaxf(m3, v.w);
    }

    float mm[4] = {m0, m1, m2, m3};
    size_t o = (size_t)b * NTOT + a4;
    u64 kk[4];
    #pragma unroll
    for (int e = 0; e < 4; e++) {
        float score = 1.0f / (1.0f + expf(-mm[e]));
        unsigned u = __float_as_uint(score);
        u = (u & 0x80000000u) ? ~u : (u | 0x80000000u);
        kk[e] = ((u64)u << 32) | (u64)(0xFFFFFFFFu - (unsigned)(a4 + e));

        int bin = (int)(score * 1024.0f);
        if (bin > 1023) bin = 1023;
        unsigned mask = __activemask();
        unsigned peers = __match_any_sync(mask, (unsigned)(b << 10) | (unsigned)bin);
        int leader = __ffs(peers) - 1;
        if ((int)(threadIdx.x & 31) == leader)
            atomicAdd(&g_hist[b * 1024 + bin], (unsigned)__popc(peers));
    }
    *(ulonglong2*)&g_key[o]     = make_ulonglong2(kk[0], kk[1]);
    *(ulonglong2*)&g_key[o + 2] = make_ulonglong2(kk[2], kk[3]);
}

// ---------------- kernel 2: compact + candidate class/box decode (full grid) ----------------
__global__ __launch_bounds__(256) void compact_kernel(
    const float* __restrict__ c0, const float* __restrict__ c1,
    const float* __restrict__ c2, const float* __restrict__ c3,
    const float* __restrict__ c4,
    const float* __restrict__ r0, const float* __restrict__ r1,
    const float* __restrict__ r2, const float* __restrict__ r3,
    const float* __restrict__ r4)
{
    const int b    = blockIdx.y;
    const int tid  = threadIdx.x;
    const int lane = tid & 31;
    const int wid  = tid >> 5;
    const unsigned* hist = g_hist + (size_t)b * 1024;

    __shared__ unsigned warpsum[8];
    __shared__ int s_tb;

    // ---- per-block redundant threshold from 1024-bin histogram ----
    int base = 1023 - tid * 4;
    unsigned h0 = hist[base], h1 = hist[base - 1], h2 = hist[base - 2], h3 = hist[base - 3];
    unsigned sum = h0 + h1 + h2 + h3;

    unsigned incl = sum;
    #pragma unroll
    for (int o = 1; o < 32; o <<= 1) {
        unsigned v = __shfl_up_sync(0xffffffffu, incl, o);
        if (lane >= o) incl += v;
    }
    if (lane == 31) warpsum[wid] = incl;
    __syncthreads();
    unsigned wbase = 0;
    #pragma unroll
    for (int ww = 0; ww < 8; ww++) wbase += (ww < wid) ? warpsum[ww] : 0u;
    unsigned cum_incl = wbase + incl;
    unsigned cum_excl = cum_incl - sum;
    if (cum_excl < (unsigned)KSEL && (unsigned)KSEL <= cum_incl) {
        unsigned running = cum_excl;
        int tb = base;
        running += h0;
        if (running < (unsigned)KSEL) { tb = base - 1; running += h1; }
        if (running < (unsigned)KSEL) { tb = base - 2; running += h2; }
        if (running < (unsigned)KSEL) { tb = base - 3; }
        s_tb = tb;
    }
    __syncthreads();
    int tb = s_tb;

    // u-space threshold: score >= tb/1024  <=>  su >= ut  (scores positive)
    float ts = (float)tb * (1.0f / 1024.0f);
    unsigned ut = __float_as_uint(ts) | 0x80000000u;

    const int a = blockIdx.x * 256 + tid;
    u64 k = 0; bool take = false;
    if (a < NTOT) {
        k = g_key[(size_t)b * NTOT + a];
        take = ((unsigned)(k >> 32) >= ut);
    }
    unsigned bal = __ballot_sync(0xffffffffu, take);
    if (bal) {
        int leader = __ffs(bal) - 1;
        int basepos = 0;
        if (lane == leader) basepos = atomicAdd(&g_cnt[b], __popc(bal));
        basepos = __shfl_sync(0xffffffffu, basepos, leader);
        if (take) {
            int pos = basepos + __popc(bal & ((1u << lane) - 1u));
            if (pos < CANDCAP) g_cand[(size_t)b * CANDCAP + pos] = k;
        }
    }

    // ---- candidate lanes: exact top-2 argmax + box decode ----
    if (take) {
        int p, hw, w, stride, lvl;
        level_of(a, p, hw, w, stride, lvl);
        const float* cp = (lvl == 0) ? c0 : (lvl == 1) ? c1 : (lvl == 2) ? c2 : (lvl == 3) ? c3 : c4;
        const float* rp = (lvl == 0) ? r0 : (lvl == 1) ? r1 : (lvl == 2) ? r2 : (lvl == 3) ? r3 : r4;

        const float* cb = cp + (size_t)b * 80 * hw + p;
        float m1 = -INFINITY, m2 = -INFINITY;
        int i1 = 0, i2 = 0;
        #pragma unroll 8
        for (int c = 0; c < 80; c++) {
            float v = __ldg(cb + (size_t)c * hw);
            if (v > m1)      { m2 = m1; i2 = i1; m1 = v; i1 = c; }
            else if (v > m2) { m2 = v; i2 = c; }
        }
        float score = 1.0f / (1.0f + expf(-m1));
        int cls = i1 + 1;
        {   // replicate jnp.argmax-over-sigmoid first-occurrence ties
            float s2 = 1.0f / (1.0f + expf(-m2));
            if (s2 == score && i2 < i1) cls = i2 + 1;
        }

        float px = (float)(p % w), py = (float)(p / w);
        float ccx = px * (float)stride + 0.5f * (float)stride;
        float ccy = py * (float)stride + 0.5f * (float)stride;
        const float* rb = rp + (size_t)b * 4 * hw + p;
        float4 box;
        box.x = ccx - __ldg(rb);
        box.y = ccy - __ldg(rb + (size_t)hw);
        box.z = ccx + __ldg(rb + (size_t)2 * hw);
        box.w = ccy + __ldg(rb + (size_t)3 * hw);

        g_cls[(size_t)b * NTOT + a] = cls;
        g_box[(size_t)b * NTOT + a] = box;
    }
}

// ---------------- kernel 3: per-batch sort + DIoU-NMS + output (+ re-zero state) ----------------
__global__ __launch_bounds__(1024, 1) void select_nms_kernel(float* __restrict__ out)
{
    const int b    = blockIdx.x;
    const int tid  = threadIdx.x;
    const int wid  = tid >> 5;
    const int lane = tid & 31;

    __shared__ u64   sm[2048];                        // 16KB: sort buf, later x1/y1/x2/y2
    __shared__ float sar[1024], scx[1024], scy[1024]; // 12KB
    __shared__ int   skeep[1024];                     // 4KB
    __shared__ unsigned warptot[32];
    __shared__ float warpred[32];
    __shared__ float s_maxc;
    __shared__ int   s_fastkept;

    float* sx1 = (float*)&sm[0];
    float* sy1 = (float*)&sm[512];
    float* sx2 = (float*)&sm[1024];
    float* sy2 = (float*)&sm[1536];

    if (tid == 0) s_fastkept = 0;

    int C = g_cnt[b]; if (C > CANDCAP) C = CANDCAP;
    u64 v0 = (tid        < C) ? g_cand[(size_t)b * CANDCAP + tid]        : 0ULL;
    u64 v1 = (tid + 1024 < C) ? g_cand[(size_t)b * CANDCAP + tid + 1024] : 0ULL;

    // re-zero replay state (all threads have read g_cnt / cand already)
    g_hist[b * 1024 + tid] = 0u;

    // ---- hybrid bitonic sort ascending over 2048 (2 elems/thread in registers) ----
    const int i1x = tid + 1024;
    for (int kk = 2; kk <= 2048; kk <<= 1) {
        for (int j = kk >> 1; j > 0; j >>= 1) {
            if (j >= 1024) {                     // kk==2048: partner in-thread
                if (v0 > v1) { u64 t = v0; v0 = v1; v1 = t; }
            } else if (j >= 32) {                // cross-warp: smem exchange
                sm[tid] = v0; sm[i1x] = v1;
                __syncthreads();
                u64 p0 = sm[tid ^ j], p1 = sm[(tid ^ j) + 1024];
                __syncthreads();
                bool tm0 = (((tid & kk) == 0) == ((tid & j) == 0));
                bool tm1 = (((i1x & kk) == 0) == ((i1x & j) == 0));
                v0 = tm0 ? (v0 < p0 ? v0 : p0) : (v0 > p0 ? v0 : p0);
                v1 = tm1 ? (v1 < p1 ? v1 : p1) : (v1 > p1 ? v1 : p1);
            } else {                             // in-warp: shuffle exchange
                u64 p0 = __shfl_xor_sync(0xffffffffu, v0, j);
                u64 p1 = __shfl_xor_sync(0xffffffffu, v1, j);
                bool tm0 = (((tid & kk) == 0) == ((tid & j) == 0));
                bool tm1 = (((i1x & kk) == 0) == ((i1x & j) == 0));
                v0 = tm0 ? (v0 < p0 ? v0 : p0) : (v0 > p0 ? v0 : p0);
                v1 = tm1 ? (v1 < p1 ? v1 : p1) : (v1 > p1 ? v1 : p1);
            }
        }
    }
    sm[tid] = v0; sm[i1x] = v1;
    __syncthreads();
    if (tid == 0) g_cnt[b] = 0;                  // re-zero for next replay

    // ---- gather rank-tid detection ----
    bool have = (tid < KSEL);
    float score = -2.0f; int mycls = 0; float4 mybox = make_float4(0, 0, 0, 0);
    if (have) {
        u64 mk = sm[2047 - tid];                 // tid-th largest
        unsigned idx = 0xFFFFFFFFu - (unsigned)(mk & 0xFFFFFFFFull);
        unsigned su  = (unsigned)(mk >> 32);
        su = (su & 0x80000000u) ? (su & 0x7FFFFFFFu) : ~su;
        score = __uint_as_float(su);
        mycls = g_cls[(size_t)b * NTOT + idx];
        mybox = g_box[(size_t)b * NTOT + idx];
    }
    bool valid = have && (score >= SCORE_THR);

    // ---- max coordinate over valid boxes ----
    float mc = valid ? fmaxf(fmaxf(mybox.x, mybox.y), fmaxf(mybox.z, mybox.w)) : -INFINITY;
    for (int o = 16; o; o >>= 1) mc = fmaxf(mc, __shfl_xor_sync(0xffffffffu, mc, o));
    if (lane == 0) warpred[wid] = mc;
    __syncthreads();
    if (tid < 32) {
        float v = warpred[tid];
        for (int o = 16; o; o >>= 1) v = fmaxf(v, __shfl_xor_sync(0xffffffffu, v, o));
        if (tid == 0) s_maxc = v;
    }
    __syncthreads();
    float maxc = s_maxc;

    // ---- class-offset shift (BEFORE area/center, like the reference) ----
    float off = (float)mycls * (maxc + 1.0f);
    float x1 = mybox.x + off, y1 = mybox.y + off;
    float x2 = mybox.z + off, y2 = mybox.w + off;
    float area = (x2 - x1 + 1.0f) * (y2 - y1 + 1.0f);
    float cx = (x1 + x2) * 0.5f, cy = (y1 + y2) * 0.5f;
    __syncthreads();   // sm reads done; alias region reusable
    sx1[tid] = x1; sy1[tid] = y1; sx2[tid] = x2; sy2[tid] = y2;
    sar[tid] = area; scx[tid] = cx; scy[tid] = cy;
    skeep[tid] = valid ? 1 : 0;
    __syncthreads();

    // ---- fast-path NMS: first FASTN rows, 4 warps, named barrier ----
    if (tid < FASTN) {
        int keepf = skeep[tid];
        int kept = 0;
        for (int i = 0; i < FASTN; i++) {
            int ki = skeep[i];
            if (ki && keepf && tid > i) {
                float xmin = fmaxf(sx1[i], x1);
                float ymin = fmaxf(sy1[i], y1);
                float xmax = fminf(sx2[i], x2);
                float ymax = fminf(sy2[i], y2);
                float inter = fmaxf(xmax - xmin, 0.0f) * fmaxf(ymax - ymin, 0.0f);
                float denom = sar[i] + area - inter;
                if (inter > IOU_THR * denom) {      // conservative: diou <= iou
                    float iou = inter / denom;
                    float dx = scx[i] - cx, dy = scy[i] - cy;
                    float idg = dx * dx + dy * dy;
                    float ox = fmaxf(sx2[i], x2) - fminf(sx1[i], x1);
                    float oy = fmaxf(sy2[i], y2) - fminf(sy1[i], y1);
                    float odg = ox * ox + oy * oy;
                    float diou = iou - idg / fmaxf(odg, 1e-12f);
                    if (diou > IOU_THR) { keepf = 0; skeep[tid] = 0; }
                }
            }
            kept += ki;
            asm volatile("bar.sync 1, 128;" ::: "memory");
            if (kept >= MAXOUT) break;              // uniform among 128
        }
        if (tid == 0) s_fastkept = kept;
    }
    __syncthreads();

    int keepj;
    if (s_fastkept >= MAXOUT) {
        keepj = skeep[tid];          // rows >= FASTN: rank >= MAXOUT -> dropped below
    } else {
        // ---- fallback: exact full 1000-row loop (reset + rerun) ----
        skeep[tid] = valid ? 1 : 0;
        __syncthreads();
        keepj = skeep[tid];
        int kept_so_far = 0;
        for (int i = 0; i < KSEL; i++) {
            int ki = skeep[i];
            if (ki && keepj && tid > i) {
                float xmin = fmaxf(sx1[i], x1);
                float ymin = fmaxf(sy1[i], y1);
                float xmax = fminf(sx2[i], x2);
                float ymax = fminf(sy2[i], y2);
                float inter = fmaxf(xmax - xmin, 0.0f) * fmaxf(ymax - ymin, 0.0f);
                float denom = sar[i] + area - inter;
                if (inter > IOU_THR * denom) {
                    float iou = inter / denom;
                    float dx = scx[i] - cx, dy = scy[i] - cy;
                    float idg = dx * dx + dy * dy;
                    float ox = fmaxf(sx2[i], x2) - fminf(sx1[i], x1);
                    float oy = fmaxf(sy2[i], y2) - fminf(sy1[i], y1);
                    float odg = ox * ox + oy * oy;
                    float diou = iou - idg / fmaxf(odg, 1e-12f);
                    if (diou > IOU_THR) { keepj = 0; skeep[tid] = 0; }
                }
            }
            kept_so_far += ki;
            __syncthreads();
            if (kept_so_far >= MAXOUT) break;       // uniform
        }
    }

    // ---- rank via ballot scan ----
    unsigned bal = __ballot_sync(0xffffffffu, keepj != 0);
    int laneprefix = __popc(bal & ((1u << lane) - 1u));
    if (lane == 0) warptot[wid] = __popc(bal);
    __syncthreads();
    if (wid == 0) {
        unsigned v = warptot[lane];
        unsigned wi = v;
        #pragma unroll
        for (int o = 1; o < 32; o <<= 1) {
            unsigned x = __shfl_up_sync(0xffffffffu, wi, o);
            if (lane >= o) wi += x;
        }
        warptot[lane] = wi - v;
    }
    __syncthreads();
    int rank = (int)warptot[wid] + laneprefix;

    // ---- output: scores [B,100] || classes [B,100] || boxes [B,100,4], all f32 ----
    float* oS = out + (size_t)b * MAXOUT;
    float* oC = out + (size_t)B * MAXOUT + (size_t)b * MAXOUT;
    float* oB = out + (size_t)2 * B * MAXOUT + (size_t)b * MAXOUT * 4;
    if (tid < MAXOUT) {
        oS[tid] = -2.0f; oC[tid] = -2.0f;
        oB[tid * 4 + 0] = -2.0f; oB[tid * 4 + 1] = -2.0f;
        oB[tid * 4 + 2] = -2.0f; oB[tid * 4 + 3] = -2.0f;
    }
    __syncthreads();
    if (keepj && rank < MAXOUT) {
        oS[rank] = score;
        oC[rank] = (float)mycls;
        oB[rank * 4 + 0] = mybox.x; oB[rank * 4 + 1] = mybox.y;
        oB[rank * 4 + 2] = mybox.z; oB[rank * 4 + 3] = mybox.w;
    }
}

// ---------------- launch ----------------
extern "C" void kernel_launch(void* const* d_in, const int* in_sizes, int n_in,
                              void* d_out, int out_size)
{
    const float* cls[5] = {0,0,0,0,0};
    const float* reg[5] = {0,0,0,0,0};
    for (int i = 0; i < n_in; i++) {
        switch (in_sizes[i]) {
            case 16384000: cls[0] = (const float*)d_in[i]; break;
            case  4096000: cls[1] = (const float*)d_in[i]; break;
            case  1024000: cls[2] = (const float*)d_in[i]; break;
            case   266240: cls[3] = (const float*)d_in[i]; break;
            case    71680: cls[4] = (const float*)d_in[i]; break;
            case   819200: reg[0] = (const float*)d_in[i]; break;
            case   204800: reg[1] = (const float*)d_in[i]; break;
            case    51200: reg[2] = (const float*)d_in[i]; break;
            case    13312: reg[3] = (const float*)d_in[i]; break;
            case     3584: reg[4] = (const float*)d_in[i]; break;
            default: break; // anchors (unused)
        }
    }
    int totalq = B * NQ;
    decode_kernel<<<(totalq + 255) / 256, 256>>>(
        cls[0], cls[1], cls[2], cls[3], cls[4]);
    compact_kernel<<<dim3((NTOT + 255) / 256, B), 256>>>(
        cls[0], cls[1], cls[2], cls[3], cls[4],
        reg[0], reg[1], reg[2], reg[3], reg[4]);
    select_nms_kernel<<<B, 1024>>>((float*)d_out);
}

// round 13
// speedup vs baseline: 1.1819x; 1.1819x over previous
#include <cuda_runtime.h>
#include <cuda_bf16.h>
#include <math.h>

#define B 16
#define NTOT 17064
#define NH   (NTOT/2)        /* 8532 threads per batch, 2 anchors each */
#define KSEL 1000
#define MAXOUT 100
#define SCORE_THR 0.05f
#define IOU_THR 0.6f
#define CANDCAP 2048
#define FASTN 128

typedef unsigned long long u64;

// ---------------- scratch (static device globals; no allocations) ----------------
__device__ u64      g_key[B * NTOT];
__device__ float4   g_box[B * NTOT];   // written sparsely (candidates only)
__device__ int      g_cls[B * NTOT];   // written sparsely (candidates only)
__device__ unsigned g_hist[B * 1024];  // zero-init at load; re-zeroed by select
__device__ int      g_cnt[B];          // zero-init at load; re-zeroed by select
__device__ u64      g_cand[B * CANDCAP];

__device__ __forceinline__ void level_of(int a, int& p, int& hw, int& w, int& stride, int& lvl)
{
    if (a < 12800)      { p = a;         hw = 12800; w = 128; stride = 8;   lvl = 0; }
    else if (a < 16000) { p = a - 12800; hw = 3200;  w = 64;  stride = 16;  lvl = 1; }
    else if (a < 16800) { p = a - 16000; hw = 800;   w = 32;  stride = 32;  lvl = 2; }
    else if (a < 17008) { p = a - 16800; hw = 208;   w = 16;  stride = 64;  lvl = 3; }
    else                { p = a - 17008; hw = 56;    w = 8;   stride = 128; lvl = 4; }
}

// ordering: A precedes B iff (vA > vB) || (vA == vB && iA < iB)
__device__ __forceinline__ bool prec(float vA, int iA, float vB, int iB)
{
    return (vA > vB) || (vA == vB && iA < iB);
}

// ---------------- kernel 1: decode = pure max-score stream (2 anchors/thread) ----------------
__global__ __launch_bounds__(256) void decode_kernel(
    const float* __restrict__ c0, const float* __restrict__ c1,
    const float* __restrict__ c2, const float* __restrict__ c3,
    const float* __restrict__ c4)
{
    int q = blockIdx.x * blockDim.x + threadIdx.x;
    if (q >= B * NH) return;
    int b  = q / NH;
    int a2 = (q - b * NH) * 2;          // 2 consecutive anchors, same level/row

    int p, hw, w, stride, lvl;
    level_of(a2, p, hw, w, stride, lvl);
    const float* cp = (lvl == 0) ? c0 : (lvl == 1) ? c1 : (lvl == 2) ? c2 : (lvl == 3) ? c3 : c4;

    const int h2 = hw >> 1;
    const float2* cb2 = (const float2*)(cp + (size_t)b * 80 * hw + p);

    // index-free max chains (1 FMNMX per class per anchor)
    float m0 = -INFINITY, m1 = -INFINITY;
    #pragma unroll 8
    for (int c = 0; c < 80; c++) {
        float2 v = __ldg(cb2 + (size_t)c * h2);
        m0 = fmaxf(m0, v.x); m1 = fmaxf(m1, v.y);
    }

    float mm[2] = {m0, m1};
    size_t o = (size_t)b * NTOT + a2;
    u64 kk[2];
    #pragma unroll
    for (int e = 0; e < 2; e++) {
        float score = 1.0f / (1.0f + expf(-mm[e]));
        unsigned u = __float_as_uint(score);
        u = (u & 0x80000000u) ? ~u : (u | 0x80000000u);
        kk[e] = ((u64)u << 32) | (u64)(0xFFFFFFFFu - (unsigned)(a2 + e));

        int bin = (int)(score * 1024.0f);
        if (bin > 1023) bin = 1023;
        unsigned mask = __activemask();
        unsigned peers = __match_any_sync(mask, (unsigned)(b << 10) | (unsigned)bin);
        int leader = __ffs(peers) - 1;
        if ((int)(threadIdx.x & 31) == leader)
            atomicAdd(&g_hist[b * 1024 + bin], (unsigned)__popc(peers));
    }
    *(ulonglong2*)&g_key[o] = make_ulonglong2(kk[0], kk[1]);
}

// ---------------- kernel 2: compact + warp-cooperative candidate decode ----------------
__global__ __launch_bounds__(256) void compact_kernel(
    const float* __restrict__ c0, const float* __restrict__ c1,
    const float* __restrict__ c2, const float* __restrict__ c3,
    const float* __restrict__ c4,
    const float* __restrict__ r0, const float* __restrict__ r1,
    const float* __restrict__ r2, const float* __restrict__ r3,
    const float* __restrict__ r4)
{
    const int b    = blockIdx.y;
    const int tid  = threadIdx.x;
    const int lane = tid & 31;
    const int wid  = tid >> 5;
    const unsigned* hist = g_hist + (size_t)b * 1024;

    __shared__ unsigned warpsum[8];
    __shared__ int s_tb;
    __shared__ int s_ca[256];     // candidate anchor ids for this block
    __shared__ int s_cc;

    if (tid == 0) s_cc = 0;

    // ---- per-block redundant threshold from 1024-bin histogram ----
    int base = 1023 - tid * 4;
    unsigned h0 = hist[base], h1 = hist[base - 1], h2 = hist[base - 2], h3 = hist[base - 3];
    unsigned sum = h0 + h1 + h2 + h3;

    unsigned incl = sum;
    #pragma unroll
    for (int o = 1; o < 32; o <<= 1) {
        unsigned v = __shfl_up_sync(0xffffffffu, incl, o);
        if (lane >= o) incl += v;
    }
    if (lane == 31) warpsum[wid] = incl;
    __syncthreads();
    unsigned wbase = 0;
    #pragma unroll
    for (int ww = 0; ww < 8; ww++) wbase += (ww < wid) ? warpsum[ww] : 0u;
    unsigned cum_incl = wbase + incl;
    unsigned cum_excl = cum_incl - sum;
    if (cum_excl < (unsigned)KSEL && (unsigned)KSEL <= cum_incl) {
        unsigned running = cum_excl;
        int tb = base;
        running += h0;
        if (running < (unsigned)KSEL) { tb = base - 1; running += h1; }
        if (running < (unsigned)KSEL) { tb = base - 2; running += h2; }
        if (running < (unsigned)KSEL) { tb = base - 3; }
        s_tb = tb;
    }
    __syncthreads();
    int tb = s_tb;

    // u-space threshold: score >= tb/1024  <=>  su >= ut  (scores positive)
    float ts = (float)tb * (1.0f / 1024.0f);
    unsigned ut = __float_as_uint(ts) | 0x80000000u;

    const int a = blockIdx.x * 256 + tid;
    u64 k = 0; bool take = false;
    if (a < NTOT) {
        k = g_key[(size_t)b * NTOT + a];
        take = ((unsigned)(k >> 32) >= ut);
    }
    unsigned bal = __ballot_sync(0xffffffffu, take);
    if (bal) {
        int leader = __ffs(bal) - 1;
        int basepos = 0;
        if (lane == leader) basepos = atomicAdd(&g_cnt[b], __popc(bal));
        basepos = __shfl_sync(0xffffffffu, basepos, leader);
        if (take) {
            int pos = basepos + __popc(bal & ((1u << lane) - 1u));
            if (pos < CANDCAP) g_cand[(size_t)b * CANDCAP + pos] = k;
            int cpos = atomicAdd(&s_cc, 1);
            s_ca[cpos] = a;
        }
    }
    __syncthreads();
    const int nc = s_cc;

    // ---- warp-cooperative candidate decode: one warp per candidate ----
    for (int ci = wid; ci < nc; ci += 8) {
        int ca = s_ca[ci];
        int p, hw, w, stride, lvl;
        level_of(ca, p, hw, w, stride, lvl);
        const float* cp = (lvl == 0) ? c0 : (lvl == 1) ? c1 : (lvl == 2) ? c2 : (lvl == 3) ? c3 : c4;
        const float* rp = (lvl == 0) ? r0 : (lvl == 1) ? r1 : (lvl == 2) ? r2 : (lvl == 3) ? r3 : r4;
        const float* cb = cp + (size_t)b * 80 * hw + p;

        // per-lane ordered top-2 over classes lane, lane+32, lane+64
        float m1 = -INFINITY, m2 = -INFINITY;
        int i1 = 0, i2 = 0;
        #pragma unroll
        for (int cc = 0; cc < 3; cc++) {
            int c = lane + cc * 32;
            if (c < 80) {
                float v = __ldg(cb + (size_t)c * hw);
                if (prec(v, c, m1, i1))      { m2 = m1; i2 = i1; m1 = v; i1 = c; }
                else if (prec(v, c, m2, i2)) { m2 = v; i2 = c; }
            }
        }
        // butterfly merge of top-2 structs (all lanes converge to same result)
        #pragma unroll
        for (int off = 16; off; off >>= 1) {
            float pm1 = __shfl_xor_sync(0xffffffffu, m1, off);
            float pm2 = __shfl_xor_sync(0xffffffffu, m2, off);
            int   pi1 = __shfl_xor_sync(0xffffffffu, i1, off);
            int   pi2 = __shfl_xor_sync(0xffffffffu, i2, off);
            float n1, n2; int j1, j2;
            if (prec(pm1, pi1, m1, i1)) {
                n1 = pm1; j1 = pi1;
                if (prec(m1, i1, pm2, pi2)) { n2 = m1; j2 = i1; }
                else                         { n2 = pm2; j2 = pi2; }
            } else {
                n1 = m1; j1 = i1;
                if (prec(m2, i2, pm1, pi1)) { n2 = m2; j2 = i2; }
                else                         { n2 = pm1; j2 = pi1; }
            }
            m1 = n1; i1 = j1; m2 = n2; i2 = j2;
        }

        if (lane == 0) {
            float score = 1.0f / (1.0f + expf(-m1));
            int cls = i1 + 1;
            {   // replicate jnp.argmax-over-sigmoid first-occurrence ties
                float s2 = 1.0f / (1.0f + expf(-m2));
                if (s2 == score && i2 < i1) cls = i2 + 1;
            }
            float px = (float)(p % w), py = (float)(p / w);
            float ccx = px * (float)stride + 0.5f * (float)stride;
            float ccy = py * (float)stride + 0.5f * (float)stride;
            const float* rb = rp + (size_t)b * 4 * hw + p;
            float4 box;
            box.x = ccx - __ldg(rb);
            box.y = ccy - __ldg(rb + (size_t)hw);
            box.z = ccx + __ldg(rb + (size_t)2 * hw);
            box.w = ccy + __ldg(rb + (size_t)3 * hw);
            g_cls[(size_t)b * NTOT + ca] = cls;
            g_box[(size_t)b * NTOT + ca] = box;
        }
    }
}

// ---------------- kernel 3: per-batch sort + DIoU-NMS + output (+ re-zero state) ----------------
__global__ __launch_bounds__(1024, 1) void select_nms_kernel(float* __restrict__ out)
{
    const int b    = blockIdx.x;
    const int tid  = threadIdx.x;
    const int wid  = tid >> 5;
    const int lane = tid & 31;

    __shared__ u64   sm[2048];                        // 16KB: sort buf, later x1/y1/x2/y2
    __shared__ float sar[1024], scx[1024], scy[1024]; // 12KB
    __shared__ int   skeep[1024];                     // 4KB
    __shared__ unsigned warptot[32];
    __shared__ float warpred[32];
    __shared__ float s_maxc;
    __shared__ int   s_fastkept;

    float* sx1 = (float*)&sm[0];
    float* sy1 = (float*)&sm[512];
    float* sx2 = (float*)&sm[1024];
    float* sy2 = (float*)&sm[1536];

    if (tid == 0) s_fastkept = 0;

    int C = g_cnt[b]; if (C > CANDCAP) C = CANDCAP;
    u64 v0 = (tid        < C) ? g_cand[(size_t)b * CANDCAP + tid]        : 0ULL;
    u64 v1 = (tid + 1024 < C) ? g_cand[(size_t)b * CANDCAP + tid + 1024] : 0ULL;

    // re-zero replay state (all threads have read g_cnt / cand already)
    g_hist[b * 1024 + tid] = 0u;

    // ---- hybrid bitonic sort ascending over 2048 (2 elems/thread in registers) ----
    const int i1x = tid + 1024;
    for (int kk = 2; kk <= 2048; kk <<= 1) {
        for (int j = kk >> 1; j > 0; j >>= 1) {
            if (j >= 1024) {                     // kk==2048: partner in-thread
                if (v0 > v1) { u64 t = v0; v0 = v1; v1 = t; }
            } else if (j >= 32) {                // cross-warp: smem exchange
                sm[tid] = v0; sm[i1x] = v1;
                __syncthreads();
                u64 p0 = sm[tid ^ j], p1 = sm[(tid ^ j) + 1024];
                __syncthreads();
                bool tm0 = (((tid & kk) == 0) == ((tid & j) == 0));
                bool tm1 = (((i1x & kk) == 0) == ((i1x & j) == 0));
                v0 = tm0 ? (v0 < p0 ? v0 : p0) : (v0 > p0 ? v0 : p0);
                v1 = tm1 ? (v1 < p1 ? v1 : p1) : (v1 > p1 ? v1 : p1);
            } else {                             // in-warp: shuffle exchange
                u64 p0 = __shfl_xor_sync(0xffffffffu, v0, j);
                u64 p1 = __shfl_xor_sync(0xffffffffu, v1, j);
                bool tm0 = (((tid & kk) == 0) == ((tid & j) == 0));
                bool tm1 = (((i1x & kk) == 0) == ((i1x & j) == 0));
                v0 = tm0 ? (v0 < p0 ? v0 : p0) : (v0 > p0 ? v0 : p0);
                v1 = tm1 ? (v1 < p1 ? v1 : p1) : (v1 > p1 ? v1 : p1);
            }
        }
    }
    sm[tid] = v0; sm[i1x] = v1;
    __syncthreads();
    if (tid == 0) g_cnt[b] = 0;                  // re-zero for next replay

    // ---- gather rank-tid detection ----
    bool have = (tid < KSEL);
    float score = -2.0f; int mycls = 0; float4 mybox = make_float4(0, 0, 0, 0);
    if (have) {
        u64 mk = sm[2047 - tid];                 // tid-th largest
        unsigned idx = 0xFFFFFFFFu - (unsigned)(mk & 0xFFFFFFFFull);
        unsigned su  = (unsigned)(mk >> 32);
        su = (su & 0x80000000u) ? (su & 0x7FFFFFFFu) : ~su;
        score = __uint_as_float(su);
        mycls = g_cls[(size_t)b * NTOT + idx];
        mybox = g_box[(size_t)b * NTOT + idx];
    }
    bool valid = have && (score >= SCORE_THR);

    // ---- max coordinate over valid boxes ----
    float mc = valid ? fmaxf(fmaxf(mybox.x, mybox.y), fmaxf(mybox.z, mybox.w)) : -INFINITY;
    for (int o = 16; o; o >>= 1) mc = fmaxf(mc, __shfl_xor_sync(0xffffffffu, mc, o));
    if (lane == 0) warpred[wid] = mc;
    __syncthreads();
    if (tid < 32) {
        float v = warpred[tid];
        for (int o = 16; o; o >>= 1) v = fmaxf(v, __shfl_xor_sync(0xffffffffu, v, o));
        if (tid == 0) s_maxc = v;
    }
    __syncthreads();
    float maxc = s_maxc;

    // ---- class-offset shift (BEFORE area/center, like the reference) ----
    float off = (float)mycls * (maxc + 1.0f);
    float x1 = mybox.x + off, y1 = mybox.y + off;
    float x2 = mybox.z + off, y2 = mybox.w + off;
    float area = (x2 - x1 + 1.0f) * (y2 - y1 + 1.0f);
    float cx = (x1 + x2) * 0.5f, cy = (y1 + y2) * 0.5f;
    __syncthreads();   // sm reads done; alias region reusable
    sx1[tid] = x1; sy1[tid] = y1; sx2[tid] = x2; sy2[tid] = y2;
    sar[tid] = area; scx[tid] = cx; scy[tid] = cy;
    skeep[tid] = valid ? 1 : 0;
    __syncthreads();

    // ---- fast-path NMS: first FASTN rows, 4 warps, named barrier ----
    if (tid < FASTN) {
        int keepf = skeep[tid];
        int kept = 0;
        for (int i = 0; i < FASTN; i++) {
            int ki = skeep[i];
            if (ki && keepf && tid > i) {
                float xmin = fmaxf(sx1[i], x1);
                float ymin = fmaxf(sy1[i], y1);
                float xmax = fminf(sx2[i], x2);
                float ymax = fminf(sy2[i], y2);
                float inter = fmaxf(xmax - xmin, 0.0f) * fmaxf(ymax - ymin, 0.0f);
                float denom = sar[i] + area - inter;
                if (inter > IOU_THR * denom) {      // conservative: diou <= iou
                    float iou = inter / denom;
                    float dx = scx[i] - cx, dy = scy[i] - cy;
                    float idg = dx * dx + dy * dy;
                    float ox = fmaxf(sx2[i], x2) - fminf(sx1[i], x1);
                    float oy = fmaxf(sy2[i], y2) - fminf(sy1[i], y1);
                    float odg = ox * ox + oy * oy;
                    float diou = iou - idg / fmaxf(odg, 1e-12f);
                    if (diou > IOU_THR) { keepf = 0; skeep[tid] = 0; }
                }
            }
            kept += ki;
            asm volatile("bar.sync 1, 128;" ::: "memory");
            if (kept >= MAXOUT) break;              // uniform among 128
        }
        if (tid == 0) s_fastkept = kept;
    }
    __syncthreads();

    int keepj;
    if (s_fastkept >= MAXOUT) {
        keepj = skeep[tid];          // rows >= FASTN: rank >= MAXOUT -> dropped below
    } else {
        // ---- fallback: exact full 1000-row loop (reset + rerun) ----
        skeep[tid] = valid ? 1 : 0;
        __syncthreads();
        keepj = skeep[tid];
        int kept_so_far = 0;
        for (int i = 0; i < KSEL; i++) {
            int ki = skeep[i];
            if (ki && keepj && tid > i) {
                float xmin = fmaxf(sx1[i], x1);
                float ymin = fmaxf(sy1[i], y1);
                float xmax = fminf(sx2[i], x2);
                float ymax = fminf(sy2[i], y2);
                float inter = fmaxf(xmax - xmin, 0.0f) * fmaxf(ymax - ymin, 0.0f);
                float denom = sar[i] + area - inter;
                if (inter > IOU_THR * denom) {
                    float iou = inter / denom;
                    float dx = scx[i] - cx, dy = scy[i] - cy;
                    float idg = dx * dx + dy * dy;
                    float ox = fmaxf(sx2[i], x2) - fminf(sx1[i], x1);
                    float oy = fmaxf(sy2[i], y2) - fminf(sy1[i], y1);
                    float odg = ox * ox + oy * oy;
                    float diou = iou - idg / fmaxf(odg, 1e-12f);
                    if (diou > IOU_THR) { keepj = 0; skeep[tid] = 0; }
                }
            }
            kept_so_far += ki;
            __syncthreads();
            if (kept_so_far >= MAXOUT) break;       // uniform
        }
    }

    // ---- rank via ballot scan ----
    unsigned bal = __ballot_sync(0xffffffffu, keepj != 0);
    int laneprefix = __popc(bal & ((1u << lane) - 1u));
    if (lane == 0) warptot[wid] = __popc(bal);
    __syncthreads();
    if (wid == 0) {
        unsigned v = warptot[lane];
        unsigned wi = v;
        #pragma unroll
        for (int o = 1; o < 32; o <<= 1) {
            unsigned x = __shfl_up_sync(0xffffffffu, wi, o);
            if (lane >= o) wi += x;
        }
        warptot[lane] = wi - v;
    }
    __syncthreads();
    int rank = (int)warptot[wid] + laneprefix;

    // ---- output: scores [B,100] || classes [B,100] || boxes [B,100,4], all f32 ----
    float* oS = out + (size_t)b * MAXOUT;
    float* oC = out + (size_t)B * MAXOUT + (size_t)b * MAXOUT;
    float* oB = out + (size_t)2 * B * MAXOUT + (size_t)b * MAXOUT * 4;
    if (tid < MAXOUT) {
        oS[tid] = -2.0f; oC[tid] = -2.0f;
        oB[tid * 4 + 0] = -2.0f; oB[tid * 4 + 1] = -2.0f;
        oB[tid * 4 + 2] = -2.0f; oB[tid * 4 + 3] = -2.0f;
    }
    __syncthreads();
    if (keepj && rank < MAXOUT) {
        oS[rank] = score;
        oC[rank] = (float)mycls;
        oB[rank * 4 + 0] = mybox.x; oB[rank * 4 + 1] = mybox.y;
        oB[rank * 4 + 2] = mybox.z; oB[rank * 4 + 3] = mybox.w;
    }
}

// ---------------- launch ----------------
extern "C" void kernel_launch(void* const* d_in, const int* in_sizes, int n_in,
                              void* d_out, int out_size)
{
    const float* cls[5] = {0,0,0,0,0};
    const float* reg[5] = {0,0,0,0,0};
    for (int i = 0; i < n_in; i++) {
        switch (in_sizes[i]) {
            case 16384000: cls[0] = (const float*)d_in[i]; break;
            case  4096000: cls[1] = (const float*)d_in[i]; break;
            case  1024000: cls[2] = (const float*)d_in[i]; break;
            case   266240: cls[3] = (const float*)d_in[i]; break;
            case    71680: cls[4] = (const float*)d_in[i]; break;
            case   819200: reg[0] = (const float*)d_in[i]; break;
            case   204800: reg[1] = (const float*)d_in[i]; break;
            case    51200: reg[2] = (const float*)d_in[i]; break;
            case    13312: reg[3] = (const float*)d_in[i]; break;
            case     3584: reg[4] = (const float*)d_in[i]; break;
            default: break; // anchors (unused)
        }
    }
    int totalh = B * NH;
    decode_kernel<<<(totalh + 255) / 256, 256>>>(
        cls[0], cls[1], cls[2], cls[3], cls[4]);
    compact_kernel<<<dim3((NTOT + 255) / 256, B), 256>>>(
        cls[0], cls[1], cls[2], cls[3], cls[4],
        reg[0], reg[1], reg[2], reg[3], reg[4]);
    select_nms_kernel<<<B, 1024>>>((float*)d_out);
}

// round 15
// speedup vs baseline: 1.2817x; 1.0845x over previous
#include <cuda_runtime.h>
#include <cuda_bf16.h>
#include <math.h>

#define B 16
#define NTOT 17064
#define NBLK 67              /* ceil(NTOT/256) */
#define KSEL 1000
#define MAXOUT 100
#define SCORE_THR 0.05f
#define IOU_THR 0.6f
#define CANDCAP 2048
#define FASTN 128

typedef unsigned long long u64;

// ---------------- scratch (static device globals; no allocations) ----------------
__device__ u64      g_key[B * NTOT];
__device__ float4   g_box[B * NTOT];   // written sparsely (candidates only)
__device__ int      g_cls[B * NTOT];   // written sparsely (candidates only)
__device__ unsigned g_hist[B * 1024];  // zero-init at load; re-zeroed by decode tail block
__device__ int      g_done[B];         // zero-init; reset by decode tail block
__device__ unsigned g_thrU[B];
__device__ int      g_cnt[B];          // zero-init; reset by select
__device__ u64      g_cand[B * CANDCAP];

__device__ __forceinline__ void level_of(int a, int& p, int& hw, int& w, int& stride, int& lvl)
{
    if (a < 12800)      { p = a;         hw = 12800; w = 128; stride = 8;   lvl = 0; }
    else if (a < 16000) { p = a - 12800; hw = 3200;  w = 64;  stride = 16;  lvl = 1; }
    else if (a < 16800) { p = a - 16000; hw = 800;   w = 32;  stride = 32;  lvl = 2; }
    else if (a < 17008) { p = a - 16800; hw = 208;   w = 16;  stride = 64;  lvl = 3; }
    else                { p = a - 17008; hw = 56;    w = 8;   stride = 128; lvl = 4; }
}

// ordering: A precedes B iff (vA > vB) || (vA == vB && iA < iB)
__device__ __forceinline__ bool prec(float vA, int iA, float vB, int iB)
{
    return (vA > vB) || (vA == vB && iA < iB);
}

// ---------------- kernel 1: decode (1 anchor/thread) + tail-block threshold ----------------
__global__ __launch_bounds__(256) void decode_kernel(
    const float* __restrict__ c0, const float* __restrict__ c1,
    const float* __restrict__ c2, const float* __restrict__ c3,
    const float* __restrict__ c4)
{
    const int b   = blockIdx.y;
    const int tid = threadIdx.x;
    const int a   = blockIdx.x * 256 + tid;
    __shared__ int s_last;
    __shared__ unsigned warpsum[8];
    __shared__ int s_tb;

    if (a < NTOT) {
        int p, hw, w, stride, lvl;
        level_of(a, p, hw, w, stride, lvl);
        const float* cp = (lvl == 0) ? c0 : (lvl == 1) ? c1 : (lvl == 2) ? c2 : (lvl == 3) ? c3 : c4;
        const float* cb = cp + (size_t)b * 80 * hw + p;

        float m = -INFINITY;
        #pragma unroll 8
        for (int c = 0; c < 80; c++)
            m = fmaxf(m, __ldg(cb + (size_t)c * hw));

        float score = 1.0f / (1.0f + expf(-m));
        unsigned u = __float_as_uint(score);
        u = (u & 0x80000000u) ? ~u : (u | 0x80000000u);
        g_key[(size_t)b * NTOT + a] = ((u64)u << 32) | (u64)(0xFFFFFFFFu - (unsigned)a);

        int bin = (int)(score * 1024.0f);
        if (bin > 1023) bin = 1023;
        unsigned mask = __activemask();
        unsigned peers = __match_any_sync(mask, (unsigned)bin);
        int leader = __ffs(peers) - 1;
        if ((int)(tid & 31) == leader)
            atomicAdd(&g_hist[b * 1024 + bin], (unsigned)__popc(peers));
    }

    // ---- tail-block election (fence so prior atomics are globally visible) ----
    __threadfence();
    __syncthreads();
    if (tid == 0) {
        int old = atomicAdd(&g_done[b], 1);
        s_last = (old == NBLK - 1);
    }
    __syncthreads();
    if (!s_last) return;

    // ---- tail block: per-batch threshold from 1024-bin hist (4 desc bins/thread) ----
    const int lane = tid & 31;
    const int wid  = tid >> 5;
    unsigned* hist = g_hist + (size_t)b * 1024;

    int base = 1023 - tid * 4;
    unsigned h0 = __ldcg(&hist[base]),     h1 = __ldcg(&hist[base - 1]);
    unsigned h2 = __ldcg(&hist[base - 2]), h3 = __ldcg(&hist[base - 3]);
    unsigned sum = h0 + h1 + h2 + h3;

    unsigned incl = sum;
    #pragma unroll
    for (int o = 1; o < 32; o <<= 1) {
        unsigned v = __shfl_up_sync(0xffffffffu, incl, o);
        if (lane >= o) incl += v;
    }
    if (lane == 31) warpsum[wid] = incl;
    __syncthreads();
    unsigned wbase = 0;
    #pragma unroll
    for (int ww = 0; ww < 8; ww++) wbase += (ww < wid) ? warpsum[ww] : 0u;
    unsigned cum_incl = wbase + incl;
    unsigned cum_excl = cum_incl - sum;
    if (cum_excl < (unsigned)KSEL && (unsigned)KSEL <= cum_incl) {
        unsigned running = cum_excl;
        int tb = base;
        running += h0;
        if (running < (unsigned)KSEL) { tb = base - 1; running += h1; }
        if (running < (unsigned)KSEL) { tb = base - 2; running += h2; }
        if (running < (unsigned)KSEL) { tb = base - 3; }
        s_tb = tb;
    }
    __syncthreads();

    // zero hist for next replay; publish threshold; reset counter
    hist[base] = 0u; hist[base - 1] = 0u; hist[base - 2] = 0u; hist[base - 3] = 0u;
    if (tid == 0) {
        float ts = (float)s_tb * (1.0f / 1024.0f);
        g_thrU[b] = __float_as_uint(ts) | 0x80000000u;
        g_done[b] = 0;
    }
}

// ---------------- kernel 2: compact + warp-cooperative candidate decode ----------------
__global__ __launch_bounds__(256) void compact_kernel(
    const float* __restrict__ c0, const float* __restrict__ c1,
    const float* __restrict__ c2, const float* __restrict__ c3,
    const float* __restrict__ c4,
    const float* __restrict__ r0, const float* __restrict__ r1,
    const float* __restrict__ r2, const float* __restrict__ r3,
    const float* __restrict__ r4)
{
    const int b    = blockIdx.y;
    const int tid  = threadIdx.x;
    const int lane = tid & 31;
    const int wid  = tid >> 5;

    __shared__ int s_ca[256];     // candidate anchor ids for this block
    __shared__ int s_cc;

    if (tid == 0) s_cc = 0;
    __syncthreads();

    const unsigned ut = g_thrU[b];
    const int a = blockIdx.x * 256 + tid;
    u64 k = 0; bool take = false;
    if (a < NTOT) {
        k = g_key[(size_t)b * NTOT + a];
        take = ((unsigned)(k >> 32) >= ut);
    }
    unsigned bal = __ballot_sync(0xffffffffu, take);
    if (bal) {
        int leader = __ffs(bal) - 1;
        int basepos = 0;
        if (lane == leader) basepos = atomicAdd(&g_cnt[b], __popc(bal));
        basepos = __shfl_sync(0xffffffffu, basepos, leader);
        if (take) {
            int pos = basepos + __popc(bal & ((1u << lane) - 1u));
            if (pos < CANDCAP) g_cand[(size_t)b * CANDCAP + pos] = k;
            int cpos = atomicAdd(&s_cc, 1);
            s_ca[cpos] = a;
        }
    }
    __syncthreads();
    const int nc = s_cc;

    // ---- warp-cooperative candidate decode: one warp per candidate ----
    for (int ci = wid; ci < nc; ci += 8) {
        int ca = s_ca[ci];
        int p, hw, w, stride, lvl;
        level_of(ca, p, hw, w, stride, lvl);
        const float* cp = (lvl == 0) ? c0 : (lvl == 1) ? c1 : (lvl == 2) ? c2 : (lvl == 3) ? c3 : c4;
        const float* rp = (lvl == 0) ? r0 : (lvl == 1) ? r1 : (lvl == 2) ? r2 : (lvl == 3) ? r3 : r4;
        const float* cb = cp + (size_t)b * 80 * hw + p;

        // per-lane ordered top-2 over classes lane, lane+32, lane+64
        float m1 = -INFINITY, m2 = -INFINITY;
        int i1 = 0, i2 = 0;
        #pragma unroll
        for (int cc = 0; cc < 3; cc++) {
            int c = lane + cc * 32;
            if (c < 80) {
                float v = __ldg(cb + (size_t)c * hw);
                if (prec(v, c, m1, i1))      { m2 = m1; i2 = i1; m1 = v; i1 = c; }
                else if (prec(v, c, m2, i2)) { m2 = v; i2 = c; }
            }
        }
        // butterfly merge of top-2 structs (all lanes converge to same result)
        #pragma unroll
        for (int off = 16; off; off >>= 1) {
            float pm1 = __shfl_xor_sync(0xffffffffu, m1, off);
            float pm2 = __shfl_xor_sync(0xffffffffu, m2, off);
            int   pi1 = __shfl_xor_sync(0xffffffffu, i1, off);
            int   pi2 = __shfl_xor_sync(0xffffffffu, i2, off);
            float n1, n2; int j1, j2;
            if (prec(pm1, pi1, m1, i1)) {
                n1 = pm1; j1 = pi1;
                if (prec(m1, i1, pm2, pi2)) { n2 = m1; j2 = i1; }
                else                         { n2 = pm2; j2 = pi2; }
            } else {
                n1 = m1; j1 = i1;
                if (prec(m2, i2, pm1, pi1)) { n2 = m2; j2 = i2; }
                else                         { n2 = pm1; j2 = pi1; }
            }
            m1 = n1; i1 = j1; m2 = n2; i2 = j2;
        }

        if (lane == 0) {
            float score = 1.0f / (1.0f + expf(-m1));
            int cls = i1 + 1;
            {   // replicate jnp.argmax-over-sigmoid first-occurrence ties
                float s2 = 1.0f / (1.0f + expf(-m2));
                if (s2 == score && i2 < i1) cls = i2 + 1;
            }
            float px = (float)(p % w), py = (float)(p / w);
            float ccx = px * (float)stride + 0.5f * (float)stride;
            float ccy = py * (float)stride + 0.5f * (float)stride;
            const float* rb = rp + (size_t)b * 4 * hw + p;
            float4 box;
            box.x = ccx - __ldg(rb);
            box.y = ccy - __ldg(rb + (size_t)hw);
            box.z = ccx + __ldg(rb + (size_t)2 * hw);
            box.w = ccy + __ldg(rb + (size_t)3 * hw);
            g_cls[(size_t)b * NTOT + ca] = cls;
            g_box[(size_t)b * NTOT + ca] = box;
        }
    }
}

// ---------------- kernel 3: per-batch sort + DIoU-NMS + output (+ reset g_cnt) ----------------
__global__ __launch_bounds__(1024, 1) void select_nms_kernel(float* __restrict__ out)
{
    const int b    = blockIdx.x;
    const int tid  = threadIdx.x;
    const int wid  = tid >> 5;
    const int lane = tid & 31;

    __shared__ u64   sm[2048];                        // 16KB: sort buf, later x1/y1/x2/y2
    __shared__ float sar[1024], scx[1024], scy[1024]; // 12KB
    __shared__ int   skeep[1024];                     // 4KB
    __shared__ unsigned warptot[32];
    __shared__ float warpred[32];
    __shared__ float s_maxc;
    __shared__ int   s_fastkept;

    float* sx1 = (float*)&sm[0];
    float* sy1 = (float*)&sm[512];
    float* sx2 = (float*)&sm[1024];
    float* sy2 = (float*)&sm[1536];

    if (tid == 0) s_fastkept = 0;

    int C = g_cnt[b]; if (C > CANDCAP) C = CANDCAP;
    u64 v0 = (tid        < C) ? g_cand[(size_t)b * CANDCAP + tid]        : 0ULL;
    u64 v1 = (tid + 1024 < C) ? g_cand[(size_t)b * CANDCAP + tid + 1024] : 0ULL;

    // ---- hybrid bitonic sort ascending over 2048 (2 elems/thread in registers) ----
    const int i1x = tid + 1024;
    for (int kk = 2; kk <= 2048; kk <<= 1) {
        for (int j = kk >> 1; j > 0; j >>= 1) {
            if (j >= 1024) {                     // kk==2048: partner in-thread
                if (v0 > v1) { u64 t = v0; v0 = v1; v1 = t; }
            } else if (j >= 32) {                // cross-warp: smem exchange
                sm[tid] = v0; sm[i1x] = v1;
                __syncthreads();
                u64 p0 = sm[tid ^ j], p1 = sm[(tid ^ j) + 1024];
                __syncthreads();
                bool tm0 = (((tid & kk) == 0) == ((tid & j) == 0));
                bool tm1 = (((i1x & kk) == 0) == ((i1x & j) == 0));
                v0 = tm0 ? (v0 < p0 ? v0 : p0) : (v0 > p0 ? v0 : p0);
                v1 = tm1 ? (v1 < p1 ? v1 : p1) : (v1 > p1 ? v1 : p1);
            } else {                             // in-warp: shuffle exchange
                u64 p0 = __shfl_xor_sync(0xffffffffu, v0, j);
                u64 p1 = __shfl_xor_sync(0xffffffffu, v1, j);
                bool tm0 = (((tid & kk) == 0) == ((tid & j) == 0));
                bool tm1 = (((i1x & kk) == 0) == ((i1x & j) == 0));
                v0 = tm0 ? (v0 < p0 ? v0 : p0) : (v0 > p0 ? v0 : p0);
                v1 = tm1 ? (v1 < p1 ? v1 : p1) : (v1 > p1 ? v1 : p1);
            }
        }
    }
    sm[tid] = v0; sm[i1x] = v1;
    __syncthreads();
    if (tid == 0) g_cnt[b] = 0;                  // reset for next replay

    // ---- gather rank-tid detection ----
    bool have = (tid < KSEL);
    float score = -2.0f; int mycls = 0; float4 mybox = make_float4(0, 0, 0, 0);
    if (have) {
        u64 mk = sm[2047 - tid];                 // tid-th largest
        unsigned idx = 0xFFFFFFFFu - (unsigned)(mk & 0xFFFFFFFFull);
        unsigned su  = (unsigned)(mk >> 32);
        su = (su & 0x80000000u) ? (su & 0x7FFFFFFFu) : ~su;
        score = __uint_as_float(su);
        mycls = g_cls[(size_t)b * NTOT + idx];
        mybox = g_box[(size_t)b * NTOT + idx];
    }
    bool valid = have && (score >= SCORE_THR);

    // ---- max coordinate over valid boxes ----
    float mc = valid ? fmaxf(fmaxf(mybox.x, mybox.y), fmaxf(mybox.z, mybox.w)) : -INFINITY;
    for (int o = 16; o; o >>= 1) mc = fmaxf(mc, __shfl_xor_sync(0xffffffffu, mc, o));
    if (lane == 0) warpred[wid] = mc;
    __syncthreads();
    if (tid < 32) {
        float v = warpred[tid];
        for (int o = 16; o; o >>= 1) v = fmaxf(v, __shfl_xor_sync(0xffffffffu, v, o));
        if (tid == 0) s_maxc = v;
    }
    __syncthreads();
    float maxc = s_maxc;

    // ---- class-offset shift (BEFORE area/center, like the reference) ----
    float off = (float)mycls * (maxc + 1.0f);
    float x1 = mybox.x + off, y1 = mybox.y + off;
    float x2 = mybox.z + off, y2 = mybox.w + off;
    float area = (x2 - x1 + 1.0f) * (y2 - y1 + 1.0f);
    float cx = (x1 + x2) * 0.5f, cy = (y1 + y2) * 0.5f;
    __syncthreads();   // sm reads done; alias region reusable
    sx1[tid] = x1; sy1[tid] = y1; sx2[tid] = x2; sy2[tid] = y2;
    sar[tid] = area; scx[tid] = cx; scy[tid] = cy;
    skeep[tid] = valid ? 1 : 0;
    __syncthreads();

    // ---- fast-path NMS: first FASTN rows, 4 warps, named barrier ----
    if (tid < FASTN) {
        int keepf = skeep[tid];
        int kept = 0;
        for (int i = 0; i < FASTN; i++) {
            int ki = skeep[i];
            if (ki && keepf && tid > i) {
                float xmin = fmaxf(sx1[i], x1);
                float ymin = fmaxf(sy1[i], y1);
                float xmax = fminf(sx2[i], x2);
                float ymax = fminf(sy2[i], y2);
                float inter = fmaxf(xmax - xmin, 0.0f) * fmaxf(ymax - ymin, 0.0f);
                float denom = sar[i] + area - inter;
                if (inter > IOU_THR * denom) {      // conservative: diou <= iou
                    float iou = inter / denom;
                    float dx = scx[i] - cx, dy = scy[i] - cy;
                    float idg = dx * dx + dy * dy;
                    float ox = fmaxf(sx2[i], x2) - fminf(sx1[i], x1);
                    float oy = fmaxf(sy2[i], y2) - fminf(sy1[i], y1);
                    float odg = ox * ox + oy * oy;
                    float diou = iou - idg / fmaxf(odg, 1e-12f);
                    if (diou > IOU_THR) { keepf = 0; skeep[tid] = 0; }
                }
            }
            kept += ki;
            asm volatile("bar.sync 1, 128;" ::: "memory");
            if (kept >= MAXOUT) break;              // uniform among 128
        }
        if (tid == 0) s_fastkept = kept;
    }
    __syncthreads();

    int keepj;
    if (s_fastkept >= MAXOUT) {
        keepj = skeep[tid];          // rows >= FASTN: rank >= MAXOUT -> dropped below
    } else {
        // ---- fallback: exact full 1000-row loop (reset + rerun) ----
        skeep[tid] = valid ? 1 : 0;
        __syncthreads();
        keepj = skeep[tid];
        int kept_so_far = 0;
        for (int i = 0; i < KSEL; i++) {
            int ki = skeep[i];
            if (ki && keepj && tid > i) {
                float xmin = fmaxf(sx1[i], x1);
                float ymin = fmaxf(sy1[i], y1);
                float xmax = fminf(sx2[i], x2);
                float ymax = fminf(sy2[i], y2);
                float inter = fmaxf(xmax - xmin, 0.0f) * fmaxf(ymax - ymin, 0.0f);
                float denom = sar[i] + area - inter;
                if (inter > IOU_THR * denom) {
                    float iou = inter / denom;
                    float dx = scx[i] - cx, dy = scy[i] - cy;
                    float idg = dx * dx + dy * dy;
                    float ox = fmaxf(sx2[i], x2) - fminf(sx1[i], x1);
                    float oy = fmaxf(sy2[i], y2) - fminf(sy1[i], y1);
                    float odg = ox * ox + oy * oy;
                    float diou = iou - idg / fmaxf(odg, 1e-12f);
                    if (diou > IOU_THR) { keepj = 0; skeep[tid] = 0; }
                }
            }
            kept_so_far += ki;
            __syncthreads();
            if (kept_so_far >= MAXOUT) break;       // uniform
        }
    }

    // ---- rank via ballot scan ----
    unsigned bal = __ballot_sync(0xffffffffu, keepj != 0);
    int laneprefix = __popc(bal & ((1u << lane) - 1u));
    if (lane == 0) warptot[wid] = __popc(bal);
    __syncthreads();
    if (wid == 0) {
        unsigned v = warptot[lane];
        unsigned wi = v;
        #pragma unroll
        for (int o = 1; o < 32; o <<= 1) {
            unsigned x = __shfl_up_sync(0xffffffffu, wi, o);
            if (lane >= o) wi += x;
        }
        warptot[lane] = wi - v;
    }
    __syncthreads();
    int rank = (int)warptot[wid] + laneprefix;

    // ---- output: scores [B,100] || classes [B,100] || boxes [B,100,4], all f32 ----
    float* oS = out + (size_t)b * MAXOUT;
    float* oC = out + (size_t)B * MAXOUT + (size_t)b * MAXOUT;
    float* oB = out + (size_t)2 * B * MAXOUT + (size_t)b * MAXOUT * 4;
    if (tid < MAXOUT) {
        oS[tid] = -2.0f; oC[tid] = -2.0f;
        oB[tid * 4 + 0] = -2.0f; oB[tid * 4 + 1] = -2.0f;
        oB[tid * 4 + 2] = -2.0f; oB[tid * 4 + 3] = -2.0f;
    }
    __syncthreads();
    if (keepj && rank < MAXOUT) {
        oS[rank] = score;
        oC[rank] = (float)mycls;
        oB[rank * 4 + 0] = mybox.x; oB[rank * 4 + 1] = mybox.y;
        oB[rank * 4 + 2] = mybox.z; oB[rank * 4 + 3] = mybox.w;
    }
}

// ---------------- launch ----------------
extern "C" void kernel_launch(void* const* d_in, const int* in_sizes, int n_in,
                              void* d_out, int out_size)
{
    const float* cls[5] = {0,0,0,0,0};
    const float* reg[5] = {0,0,0,0,0};
    for (int i = 0; i < n_in; i++) {
        switch (in_sizes[i]) {
            case 16384000: cls[0] = (const float*)d_in[i]; break;
            case  4096000: cls[1] = (const float*)d_in[i]; break;
            case  1024000: cls[2] = (const float*)d_in[i]; break;
            case   266240: cls[3] = (const float*)d_in[i]; break;
            case    71680: cls[4] = (const float*)d_in[i]; break;
            case   819200: reg[0] = (const float*)d_in[i]; break;
            case   204800: reg[1] = (const float*)d_in[i]; break;
            case    51200: reg[2] = (const float*)d_in[i]; break;
            case    13312: reg[3] = (const float*)d_in[i]; break;
            case     3584: reg[4] = (const float*)d_in[i]; break;
            default: break; // anchors (unused)
        }
    }
    dim3 fg(NBLK, B);
    decode_kernel<<<fg, 256>>>(cls[0], cls[1], cls[2], cls[3], cls[4]);
    compact_kernel<<<fg, 256>>>(
        cls[0], cls[1], cls[2], cls[3], cls[4],
        reg[0], reg[1], reg[2], reg[3], reg[4]);
    select_nms_kernel<<<B, 1024>>>((float*)d_out);
}

// round 17
// speedup vs baseline: 1.3573x; 1.0589x over previous
#include <cuda_runtime.h>
#include <cuda_bf16.h>
#include <math.h>

#define B 16
#define NTOT 17064
#define NBLK 67              /* ceil(NTOT/256) */
#define KSEL 1000
#define MAXOUT 100
#define SCORE_THR 0.05f
#define IOU_THR 0.6f
#define CANDCAP 2048
#define FASTN 128

typedef unsigned long long u64;

// ---------------- scratch (static device globals; no allocations) ----------------
__device__ u64      g_key[B * NTOT];
__device__ float4   g_box[B * NTOT];   // written sparsely (candidates only)
__device__ int      g_cls[B * NTOT];   // written sparsely (candidates only)
__device__ unsigned g_hist[B * 1024];  // zero-init at load; re-zeroed by decode tail block
__device__ int      g_done[B];         // zero-init; reset by decode tail block
__device__ unsigned g_thrU[B];
__device__ int      g_cnt[B];          // zero-init; reset by select
__device__ u64      g_cand[B * CANDCAP];

__device__ __forceinline__ void level_of(int a, int& p, int& hw, int& w, int& stride, int& lvl)
{
    if (a < 12800)      { p = a;         hw = 12800; w = 128; stride = 8;   lvl = 0; }
    else if (a < 16000) { p = a - 12800; hw = 3200;  w = 64;  stride = 16;  lvl = 1; }
    else if (a < 16800) { p = a - 16000; hw = 800;   w = 32;  stride = 32;  lvl = 2; }
    else if (a < 17008) { p = a - 16800; hw = 208;   w = 16;  stride = 64;  lvl = 3; }
    else                { p = a - 17008; hw = 56;    w = 8;   stride = 128; lvl = 4; }
}

// ordering: A precedes B iff (vA > vB) || (vA == vB && iA < iB)
__device__ __forceinline__ bool prec(float vA, int iA, float vB, int iB)
{
    return (vA > vB) || (vA == vB && iA < iB);
}

// ---------------- kernel 1: decode (1 anchor/thread) + tail-block threshold ----------------
__global__ __launch_bounds__(256) void decode_kernel(
    const float* __restrict__ c0, const float* __restrict__ c1,
    const float* __restrict__ c2, const float* __restrict__ c3,
    const float* __restrict__ c4)
{
    const int b   = blockIdx.y;
    const int tid = threadIdx.x;
    const int a   = blockIdx.x * 256 + tid;
    __shared__ int s_last;
    __shared__ unsigned warpsum[8];
    __shared__ int s_tb;

    if (a < NTOT) {
        int p, hw, w, stride, lvl;
        level_of(a, p, hw, w, stride, lvl);
        const float* cp = (lvl == 0) ? c0 : (lvl == 1) ? c1 : (lvl == 2) ? c2 : (lvl == 3) ? c3 : c4;
        const float* cb = cp + (size_t)b * 80 * hw + p;

        float m = -INFINITY;
        #pragma unroll 8
        for (int c = 0; c < 80; c++)
            m = fmaxf(m, __ldcs(cb + (size_t)c * hw));

        float score = 1.0f / (1.0f + expf(-m));
        unsigned u = __float_as_uint(score);
        u = (u & 0x80000000u) ? ~u : (u | 0x80000000u);
        g_key[(size_t)b * NTOT + a] = ((u64)u << 32) | (u64)(0xFFFFFFFFu - (unsigned)a);

        int bin = (int)(score * 1024.0f);
        if (bin > 1023) bin = 1023;
        unsigned mask = __activemask();
        unsigned peers = __match_any_sync(mask, (unsigned)bin);
        int leader = __ffs(peers) - 1;
        if ((int)(tid & 31) == leader)
            atomicAdd(&g_hist[b * 1024 + bin], (unsigned)__popc(peers));
    }

    // ---- tail-block election (fence so prior atomics are globally visible) ----
    __threadfence();
    __syncthreads();
    if (tid == 0) {
        int old = atomicAdd(&g_done[b], 1);
        s_last = (old == NBLK - 1);
    }
    __syncthreads();
    if (!s_last) return;

    // ---- tail block: per-batch threshold from 1024-bin hist (4 desc bins/thread) ----
    const int lane = tid & 31;
    const int wid  = tid >> 5;
    unsigned* hist = g_hist + (size_t)b * 1024;

    int base = 1023 - tid * 4;
    unsigned h0 = __ldcg(&hist[base]),     h1 = __ldcg(&hist[base - 1]);
    unsigned h2 = __ldcg(&hist[base - 2]), h3 = __ldcg(&hist[base - 3]);
    unsigned sum = h0 + h1 + h2 + h3;

    unsigned incl = sum;
    #pragma unroll
    for (int o = 1; o < 32; o <<= 1) {
        unsigned v = __shfl_up_sync(0xffffffffu, incl, o);
        if (lane >= o) incl += v;
    }
    if (lane == 31) warpsum[wid] = incl;
    __syncthreads();
    unsigned wbase = 0;
    #pragma unroll
    for (int ww = 0; ww < 8; ww++) wbase += (ww < wid) ? warpsum[ww] : 0u;
    unsigned cum_incl = wbase + incl;
    unsigned cum_excl = cum_incl - sum;
    if (cum_excl < (unsigned)KSEL && (unsigned)KSEL <= cum_incl) {
        unsigned running = cum_excl;
        int tb = base;
        running += h0;
        if (running < (unsigned)KSEL) { tb = base - 1; running += h1; }
        if (running < (unsigned)KSEL) { tb = base - 2; running += h2; }
        if (running < (unsigned)KSEL) { tb = base - 3; }
        s_tb = tb;
    }
    __syncthreads();

    // zero hist for next replay; publish threshold; reset counter
    hist[base] = 0u; hist[base - 1] = 0u; hist[base - 2] = 0u; hist[base - 3] = 0u;
    if (tid == 0) {
        float ts = (float)s_tb * (1.0f / 1024.0f);
        g_thrU[b] = __float_as_uint(ts) | 0x80000000u;
        g_done[b] = 0;
    }
}

// ---------------- kernel 2: compact + warp-cooperative candidate decode ----------------
__global__ __launch_bounds__(256) void compact_kernel(
    const float* __restrict__ c0, const float* __restrict__ c1,
    const float* __restrict__ c2, const float* __restrict__ c3,
    const float* __restrict__ c4,
    const float* __restrict__ r0, const float* __restrict__ r1,
    const float* __restrict__ r2, const float* __restrict__ r3,
    const float* __restrict__ r4)
{
    const int b    = blockIdx.y;
    const int tid  = threadIdx.x;
    const int lane = tid & 31;
    const int wid  = tid >> 5;

    __shared__ int s_ca[256];     // candidate anchor ids for this block
    __shared__ int s_cc;

    if (tid == 0) s_cc = 0;
    __syncthreads();

    const unsigned ut = g_thrU[b];
    const int a = blockIdx.x * 256 + tid;
    u64 k = 0; bool take = false;
    if (a < NTOT) {
        k = g_key[(size_t)b * NTOT + a];
        take = ((unsigned)(k >> 32) >= ut);
    }
    unsigned bal = __ballot_sync(0xffffffffu, take);
    if (bal) {
        int leader = __ffs(bal) - 1;
        int basepos = 0;
        if (lane == leader) basepos = atomicAdd(&g_cnt[b], __popc(bal));
        basepos = __shfl_sync(0xffffffffu, basepos, leader);
        if (take) {
            int pos = basepos + __popc(bal & ((1u << lane) - 1u));
            if (pos < CANDCAP) g_cand[(size_t)b * CANDCAP + pos] = k;
            int cpos = atomicAdd(&s_cc, 1);
            s_ca[cpos] = a;
        }
    }
    __syncthreads();
    const int nc = s_cc;

    // ---- warp-cooperative candidate decode: one warp per candidate ----
    for (int ci = wid; ci < nc; ci += 8) {
        int ca = s_ca[ci];
        int p, hw, w, stride, lvl;
        level_of(ca, p, hw, w, stride, lvl);
        const float* cp = (lvl == 0) ? c0 : (lvl == 1) ? c1 : (lvl == 2) ? c2 : (lvl == 3) ? c3 : c4;
        const float* rp = (lvl == 0) ? r0 : (lvl == 1) ? r1 : (lvl == 2) ? r2 : (lvl == 3) ? r3 : r4;
        const float* cb = cp + (size_t)b * 80 * hw + p;

        // per-lane ordered top-2 over classes lane, lane+32, lane+64
        float m1 = -INFINITY, m2 = -INFINITY;
        int i1 = 0, i2 = 0;
        #pragma unroll
        for (int cc = 0; cc < 3; cc++) {
            int c = lane + cc * 32;
            if (c < 80) {
                float v = __ldg(cb + (size_t)c * hw);
                if (prec(v, c, m1, i1))      { m2 = m1; i2 = i1; m1 = v; i1 = c; }
                else if (prec(v, c, m2, i2)) { m2 = v; i2 = c; }
            }
        }
        // butterfly merge of top-2 structs (all lanes converge to same result)
        #pragma unroll
        for (int off = 16; off; off >>= 1) {
            float pm1 = __shfl_xor_sync(0xffffffffu, m1, off);
            float pm2 = __shfl_xor_sync(0xffffffffu, m2, off);
            int   pi1 = __shfl_xor_sync(0xffffffffu, i1, off);
            int   pi2 = __shfl_xor_sync(0xffffffffu, i2, off);
            float n1, n2; int j1, j2;
            if (prec(pm1, pi1, m1, i1)) {
                n1 = pm1; j1 = pi1;
                if (prec(m1, i1, pm2, pi2)) { n2 = m1; j2 = i1; }
                else                         { n2 = pm2; j2 = pi2; }
            } else {
                n1 = m1; j1 = i1;
                if (prec(m2, i2, pm1, pi1)) { n2 = m2; j2 = i2; }
                else                         { n2 = pm1; j2 = pi1; }
            }
            m1 = n1; i1 = j1; m2 = n2; i2 = j2;
        }

        if (lane == 0) {
            float score = 1.0f / (1.0f + expf(-m1));
            int cls = i1 + 1;
            {   // replicate jnp.argmax-over-sigmoid first-occurrence ties
                float s2 = 1.0f / (1.0f + expf(-m2));
                if (s2 == score && i2 < i1) cls = i2 + 1;
            }
            float px = (float)(p % w), py = (float)(p / w);
            float ccx = px * (float)stride + 0.5f * (float)stride;
            float ccy = py * (float)stride + 0.5f * (float)stride;
            const float* rb = rp + (size_t)b * 4 * hw + p;
            float4 box;
            box.x = ccx - __ldg(rb);
            box.y = ccy - __ldg(rb + (size_t)hw);
            box.z = ccx + __ldg(rb + (size_t)2 * hw);
            box.w = ccy + __ldg(rb + (size_t)3 * hw);
            g_cls[(size_t)b * NTOT + ca] = cls;
            g_box[(size_t)b * NTOT + ca] = box;
        }
    }
}

// ---------------- kernel 3: per-batch sort + mask-NMS + output (+ reset g_cnt) ----------------
__global__ __launch_bounds__(1024, 1) void select_nms_kernel(float* __restrict__ out)
{
    const int b    = blockIdx.x;
    const int tid  = threadIdx.x;
    const int wid  = tid >> 5;
    const int lane = tid & 31;

    __shared__ u64   sm[2048];                        // 16KB: sort buf, later x1/y1/x2/y2
    __shared__ float sar[1024], scx[1024], scy[1024]; // 12KB
    __shared__ int   skeep[1024];                     // 4KB
    __shared__ unsigned supm[FASTN][4];               // 2KB suppression bitmasks
    __shared__ unsigned s_validm[4];
    __shared__ unsigned s_keepm[4];
    __shared__ unsigned warptot[32];
    __shared__ float warpred[32];
    __shared__ float s_maxc;
    __shared__ int   s_fastkept;

    float* sx1 = (float*)&sm[0];
    float* sy1 = (float*)&sm[512];
    float* sx2 = (float*)&sm[1024];
    float* sy2 = (float*)&sm[1536];

    if (tid == 0) s_fastkept = 0;
    if (tid < FASTN * 4) ((unsigned*)supm)[tid] = 0u;

    int C = g_cnt[b]; if (C > CANDCAP) C = CANDCAP;
    u64 v0 = (tid        < C) ? g_cand[(size_t)b * CANDCAP + tid]        : 0ULL;
    u64 v1 = (tid + 1024 < C) ? g_cand[(size_t)b * CANDCAP + tid + 1024] : 0ULL;

    // ---- hybrid bitonic sort ascending over 2048 (2 elems/thread in registers) ----
    const int i1x = tid + 1024;
    for (int kk = 2; kk <= 2048; kk <<= 1) {
        for (int j = kk >> 1; j > 0; j >>= 1) {
            if (j >= 1024) {                     // kk==2048: partner in-thread
                if (v0 > v1) { u64 t = v0; v0 = v1; v1 = t; }
            } else if (j >= 32) {                // cross-warp: smem exchange
                sm[tid] = v0; sm[i1x] = v1;
                __syncthreads();
                u64 p0 = sm[tid ^ j], p1 = sm[(tid ^ j) + 1024];
                __syncthreads();
                bool tm0 = (((tid & kk) == 0) == ((tid & j) == 0));
                bool tm1 = (((i1x & kk) == 0) == ((i1x & j) == 0));
                v0 = tm0 ? (v0 < p0 ? v0 : p0) : (v0 > p0 ? v0 : p0);
                v1 = tm1 ? (v1 < p1 ? v1 : p1) : (v1 > p1 ? v1 : p1);
            } else {                             // in-warp: shuffle exchange
                u64 p0 = __shfl_xor_sync(0xffffffffu, v0, j);
                u64 p1 = __shfl_xor_sync(0xffffffffu, v1, j);
                bool tm0 = (((tid & kk) == 0) == ((tid & j) == 0));
                bool tm1 = (((i1x & kk) == 0) == ((i1x & j) == 0));
                v0 = tm0 ? (v0 < p0 ? v0 : p0) : (v0 > p0 ? v0 : p0);
                v1 = tm1 ? (v1 < p1 ? v1 : p1) : (v1 > p1 ? v1 : p1);
            }
        }
    }
    sm[tid] = v0; sm[i1x] = v1;
    __syncthreads();
    if (tid == 0) g_cnt[b] = 0;                  // reset for next replay

    // ---- gather rank-tid detection ----
    bool have = (tid < KSEL);
    float score = -2.0f; int mycls = 0; float4 mybox = make_float4(0, 0, 0, 0);
    if (have) {
        u64 mk = sm[2047 - tid];                 // tid-th largest
        unsigned idx = 0xFFFFFFFFu - (unsigned)(mk & 0xFFFFFFFFull);
        unsigned su  = (unsigned)(mk >> 32);
        su = (su & 0x80000000u) ? (su & 0x7FFFFFFFu) : ~su;
        score = __uint_as_float(su);
        mycls = g_cls[(size_t)b * NTOT + idx];
        mybox = g_box[(size_t)b * NTOT + idx];
    }
    bool valid = have && (score >= SCORE_THR);

    // ---- max coordinate over valid boxes ----
    float mc = valid ? fmaxf(fmaxf(mybox.x, mybox.y), fmaxf(mybox.z, mybox.w)) : -INFINITY;
    for (int o = 16; o; o >>= 1) mc = fmaxf(mc, __shfl_xor_sync(0xffffffffu, mc, o));
    if (lane == 0) warpred[wid] = mc;
    __syncthreads();
    if (tid < 32) {
        float v = warpred[tid];
        for (int o = 16; o; o >>= 1) v = fmaxf(v, __shfl_xor_sync(0xffffffffu, v, o));
        if (tid == 0) s_maxc = v;
    }
    __syncthreads();
    float maxc = s_maxc;

    // ---- class-offset shift (BEFORE area/center, like the reference) ----
    float off = (float)mycls * (maxc + 1.0f);
    float x1 = mybox.x + off, y1 = mybox.y + off;
    float x2 = mybox.z + off, y2 = mybox.w + off;
    float area = (x2 - x1 + 1.0f) * (y2 - y1 + 1.0f);
    float cx = (x1 + x2) * 0.5f, cy = (y1 + y2) * 0.5f;
    __syncthreads();   // sm reads done; alias region reusable
    sx1[tid] = x1; sy1[tid] = y1; sx2[tid] = x2; sy2[tid] = y2;
    sar[tid] = area; scx[tid] = cx; scy[tid] = cy;
    skeep[tid] = valid ? 1 : 0;
    // valid bitmask of rows 0..127 (warps 0..3 full)
    if (tid < FASTN) {
        unsigned vb = __ballot_sync(0xffffffffu, valid);
        if (lane == 0) s_validm[wid] = vb;
    }
    __syncthreads();

    // ---- fast-path NMS: suppression bitmask over first FASTN rows ----
    // 8 threads per row i; each covers j = i+1+k, i+1+k+8, ... (barrier-free loop)
    {
        int i = tid >> 3, k = tid & 7;
        float ix1 = sx1[i], iy1 = sy1[i], ix2 = sx2[i], iy2 = sy2[i];
        float iar = sar[i], icx = scx[i], icy = scy[i];
        for (int j = i + 1 + k; j < FASTN; j += 8) {
            float xmin = fmaxf(ix1, sx1[j]);
            float ymin = fmaxf(iy1, sy1[j]);
            float xmax = fminf(ix2, sx2[j]);
            float ymax = fminf(iy2, sy2[j]);
            float inter = fmaxf(xmax - xmin, 0.0f) * fmaxf(ymax - ymin, 0.0f);
            float denom = iar + sar[j] - inter;
            if (inter > IOU_THR * denom) {       // conservative: diou <= iou
                float iou = inter / denom;
                float dx = icx - scx[j], dy = icy - scy[j];
                float idg = dx * dx + dy * dy;
                float ox = fmaxf(ix2, sx2[j]) - fminf(ix1, sx1[j]);
                float oy = fmaxf(iy2, sy2[j]) - fminf(iy1, sy1[j]);
                float odg = ox * ox + oy * oy;
                float diou = iou - idg / fmaxf(odg, 1e-12f);
                if (diou > IOU_THR)
                    atomicOr(&supm[i][j >> 5], 1u << (j & 31));
            }
        }
    }
    __syncthreads();
    // serial greedy resolution on one thread (128 tiny iterations, register bitset)
    if (tid == 0) {
        unsigned kb0 = s_validm[0], kb1 = s_validm[1], kb2 = s_validm[2], kb3 = s_validm[3];
        #pragma unroll 4
        for (int i = 0; i < FASTN; i++) {
            unsigned w = (i < 32) ? kb0 : (i < 64) ? kb1 : (i < 96) ? kb2 : kb3;
            if ((w >> (i & 31)) & 1u) {
                kb0 &= ~supm[i][0]; kb1 &= ~supm[i][1];
                kb2 &= ~supm[i][2]; kb3 &= ~supm[i][3];
            }
        }
        s_keepm[0] = kb0; s_keepm[1] = kb1; s_keepm[2] = kb2; s_keepm[3] = kb3;
        s_fastkept = __popc(kb0) + __popc(kb1) + __popc(kb2) + __popc(kb3);
    }
    __syncthreads();

    int keepj;
    if (s_fastkept >= MAXOUT) {
        // rows < FASTN exact from bitmask; rows >= FASTN get rank >= MAXOUT -> dropped
        keepj = (tid < FASTN) ? (int)((s_keepm[tid >> 5] >> (tid & 31)) & 1u) : skeep[tid];
    } else {
        // ---- fallback: exact full 1000-row loop (skeep untouched by mask path) ----
        keepj = skeep[tid];
        int kept_so_far = 0;
        for (int i = 0; i < KSEL; i++) {
            int ki = skeep[i];
            if (ki && keepj && tid > i) {
                float xmin = fmaxf(sx1[i], x1);
                float ymin = fmaxf(sy1[i], y1);
                float xmax = fminf(sx2[i], x2);
                float ymax = fminf(sy2[i], y2);
                float inter = fmaxf(xmax - xmin, 0.0f) * fmaxf(ymax - ymin, 0.0f);
                float denom = sar[i] + area - inter;
                if (inter > IOU_THR * denom) {
                    float iou = inter / denom;
                    float dx = scx[i] - cx, dy = scy[i] - cy;
                    float idg = dx * dx + dy * dy;
                    float ox = fmaxf(sx2[i], x2) - fminf(sx1[i], x1);
                    float oy = fmaxf(sy2[i], y2) - fminf(sy1[i], y1);
                    float odg = ox * ox + oy * oy;
                    float diou = iou - idg / fmaxf(odg, 1e-12f);
                    if (diou > IOU_THR) { keepj = 0; skeep[tid] = 0; }
                }
            }
            kept_so_far += ki;
            __syncthreads();
            if (kept_so_far >= MAXOUT) break;       // uniform
        }
    }

    // ---- rank via ballot scan ----
    unsigned bal = __ballot_sync(0xffffffffu, keepj != 0);
    int laneprefix = __popc(bal & ((1u << lane) - 1u));
    if (lane == 0) warptot[wid] = __popc(bal);
    __syncthreads();
    if (wid == 0) {
        unsigned v = warptot[lane];
        unsigned wi = v;
        #pragma unroll
        for (int o = 1; o < 32; o <<= 1) {
            unsigned x = __shfl_up_sync(0xffffffffu, wi, o);
            if (lane >= o) wi += x;
        }
        warptot[lane] = wi - v;
    }
    __syncthreads();
    int rank = (int)warptot[wid] + laneprefix;

    // ---- output: scores [B,100] || classes [B,100] || boxes [B,100,4], all f32 ----
    float* oS = out + (size_t)b * MAXOUT;
    float* oC = out + (size_t)B * MAXOUT + (size_t)b * MAXOUT;
    float* oB = out + (size_t)2 * B * MAXOUT + (size_t)b * MAXOUT * 4;
    if (tid < MAXOUT) {
        oS[tid] = -2.0f; oC[tid] = -2.0f;
        oB[tid * 4 + 0] = -2.0f; oB[tid * 4 + 1] = -2.0f;
        oB[tid * 4 + 2] = -2.0f; oB[tid * 4 + 3] = -2.0f;
    }
    __syncthreads();
    if (keepj && rank < MAXOUT) {
        oS[rank] = score;
        oC[rank] = (float)mycls;
        oB[rank * 4 + 0] = mybox.x; oB[rank * 4 + 1] = mybox.y;
        oB[rank * 4 + 2] = mybox.z; oB[rank * 4 + 3] = mybox.w;
    }
}

// ---------------- launch ----------------
extern "C" void kernel_launch(void* const* d_in, const int* in_sizes, int n_in,
                              void* d_out, int out_size)
{
    const float* cls[5] = {0,0,0,0,0};
    const float* reg[5] = {0,0,0,0,0};
    for (int i = 0; i < n_in; i++) {
        switch (in_sizes[i]) {
            case 16384000: cls[0] = (const float*)d_in[i]; break;
            case  4096000: cls[1] = (const float*)d_in[i]; break;
            case  1024000: cls[2] = (const float*)d_in[i]; break;
            case   266240: cls[3] = (const float*)d_in[i]; break;
            case    71680: cls[4] = (const float*)d_in[i]; break;
            case   819200: reg[0] = (const float*)d_in[i]; break;
            case   204800: reg[1] = (const float*)d_in[i]; break;
            case    51200: reg[2] = (const float*)d_in[i]; break;
            case    13312: reg[3] = (const float*)d_in[i]; break;
            case     3584: reg[4] = (const float*)d_in[i]; break;
            default: break; // anchors (unused)
        }
    }
    dim3 fg(NBLK, B);
    decode_kernel<<<fg, 256>>>(cls[0], cls[1], cls[2], cls[3], cls[4]);
    compact_kernel<<<fg, 256>>>(
        cls[0], cls[1], cls[2], cls[3], cls[4],
        reg[0], reg[1], reg[2], reg[3], reg[4]);
    select_nms_kernel<<<B, 1024>>>((float*)d_out);
}